// round 5
// baseline (speedup 1.0000x reference)
#include <cuda_runtime.h>
#include <cstddef>

#define BDIM 1024
#define SDIM 258
#define IDIM 512
#define HDIM 512
#define G4   (4*HDIM)   // 2048

// ---------------- scratch (device globals; no allocations allowed) ----------
__device__ __align__(16) float g_Acat[(size_t)BDIM*(IDIM+HDIM)];   // [char | h_gather]  1024x1024
__device__ __align__(16) float g_gates_r[(size_t)BDIM*G4];         // 1024x2048
__device__ __align__(16) float g_gates_l[(size_t)BDIM*G4];         // 1024x2048
__device__ __align__(16) float g_hlcat[(size_t)BDIM*(2*HDIM)];     // [h_r | h_l] 1024x1024

__device__ __forceinline__ float sigf(float x) { return 1.0f / (1.0f + expf(-x)); }

// ---------------- 1) bulk copy of both stacks into the output ---------------
__global__ void copy_stacks_kernel(const float4* __restrict__ sh,
                                   const float4* __restrict__ sc,
                                   float4* __restrict__ dh,
                                   float4* __restrict__ dc,
                                   size_t n4) {
    size_t i = (size_t)blockIdx.x * blockDim.x + threadIdx.x;
    size_t stride = (size_t)gridDim.x * blockDim.x;
    for (; i < n4; i += stride) {
        dh[i] = sh[i];
        dc[i] = sc[i];
    }
}

// ---------------- 2) gather A = [char | stack_hidden[b, pos[b]]] ------------
__global__ void gather_kernel(const float* __restrict__ ch,
                              const float* __restrict__ sh,
                              const int* __restrict__ pos) {
    int idx = blockIdx.x * blockDim.x + threadIdx.x;   // over B*H/4
    if (idx >= BDIM * (HDIM / 4)) return;
    int b = idx / (HDIM / 4);
    int q = idx % (HDIM / 4);
    const float4* chv = (const float4*)ch;
    const float4* shv = (const float4*)sh;
    float4* Ac = (float4*)g_Acat;
    int p = pos[b];
    float4 cv = chv[(size_t)b * (IDIM / 4) + q];
    float4 hv = shv[((size_t)b * SDIM + p) * (HDIM / 4) + q];
    Ac[(size_t)b * 256 + q]       = cv;   // cols [0,512)
    Ac[(size_t)b * 256 + 128 + q] = hv;   // cols [512,1024)
}

// ---------------- 3) tiled fp32 GEMM: C = A @ W^T + b1(+b2), opt tanh -------
// A: (M,K) row-major.  W(n,k) = k<K1 ? W1[n*K1+k] : W2[n*(K-K1)+(k-K1)]
// BM=128, BN=64, BK=16, 256 threads, 8x4 micro-tile per thread.
#define BM 128
#define BN 64
#define BK 16
#define TM 8
#define TN 4

__global__ __launch_bounds__(256)
void gemm_ws_kernel(const float* __restrict__ A,
                    const float* __restrict__ W1,
                    const float* __restrict__ W2,
                    int K1, int K,
                    const float* __restrict__ b1,
                    const float* __restrict__ b2,
                    float* __restrict__ C,
                    int N, int act) {
    __shared__ __align__(16) float As[BK][BM];
    __shared__ __align__(16) float Bs[BK][BN];

    int tid = threadIdx.x;
    int tx = tid & 15;      // 0..15 -> columns (TN=4 each)
    int ty = tid >> 4;      // 0..15 -> rows    (TM=8 each)
    int block_m = blockIdx.y * BM;
    int block_n = blockIdx.x * BN;

    float acc[TM][TN];
    #pragma unroll
    for (int i = 0; i < TM; i++)
        #pragma unroll
        for (int j = 0; j < TN; j++) acc[i][j] = 0.0f;

    for (int k0 = 0; k0 < K; k0 += BK) {
        // --- load A tile (BM x BK) as float4, store transposed ---
        #pragma unroll
        for (int it = 0; it < 2; it++) {
            int li = tid + it * 256;       // 0..511
            int m  = li >> 2;              // 0..127
            int kq = (li & 3) << 2;        // 0,4,8,12
            float4 v = *reinterpret_cast<const float4*>(
                &A[(size_t)(block_m + m) * K + k0 + kq]);
            As[kq + 0][m] = v.x; As[kq + 1][m] = v.y;
            As[kq + 2][m] = v.z; As[kq + 3][m] = v.w;
        }
        // --- load W tile (BN x BK), split-source ---
        {
            int li = tid;                  // 0..255
            int n  = li >> 2;              // 0..63
            int kq = (li & 3) << 2;
            int kk = k0 + kq;
            const float* Wp; int kw, Kw;
            if (kk < K1) { Wp = W1; kw = kk;       Kw = K1;     }
            else         { Wp = W2; kw = kk - K1;  Kw = K - K1; }
            float4 v = *reinterpret_cast<const float4*>(
                &Wp[(size_t)(block_n + n) * Kw + kw]);
            Bs[kq + 0][n] = v.x; Bs[kq + 1][n] = v.y;
            Bs[kq + 2][n] = v.z; Bs[kq + 3][n] = v.w;
        }
        __syncthreads();

        #pragma unroll
        for (int kk = 0; kk < BK; kk++) {
            float4 a0 = *reinterpret_cast<const float4*>(&As[kk][ty * TM]);
            float4 a1 = *reinterpret_cast<const float4*>(&As[kk][ty * TM + 4]);
            float4 bv = *reinterpret_cast<const float4*>(&Bs[kk][tx * TN]);
            float a[TM] = {a0.x, a0.y, a0.z, a0.w, a1.x, a1.y, a1.z, a1.w};
            float bcol[TN] = {bv.x, bv.y, bv.z, bv.w};
            #pragma unroll
            for (int i = 0; i < TM; i++)
                #pragma unroll
                for (int j = 0; j < TN; j++)
                    acc[i][j] += a[i] * bcol[j];
        }
        __syncthreads();
    }

    // --- epilogue: bias (+bias2), optional tanh, float4 store ---
    float bb[TN];
    #pragma unroll
    for (int j = 0; j < TN; j++) {
        int n = block_n + tx * TN + j;
        float bsum = b1 ? b1[n] : 0.0f;
        if (b2) bsum += b2[n];
        bb[j] = bsum;
    }
    #pragma unroll
    for (int i = 0; i < TM; i++) {
        int m = block_m + ty * TM + i;
        float r[TN];
        #pragma unroll
        for (int j = 0; j < TN; j++) {
            float x = acc[i][j] + bb[j];
            if (act == 1) x = tanhf(x);
            r[j] = x;
        }
        *reinterpret_cast<float4*>(&C[(size_t)m * N + block_n + tx * TN]) =
            make_float4(r[0], r[1], r[2], r[3]);
    }
}

// ---------------- 4) LSTM elementwise + scatter + build [h_r|h_l] ----------
__global__ void lstm_elem_kernel(const float* __restrict__ stack_cell,
                                 const int* __restrict__ pos,
                                 float* __restrict__ out_h,
                                 float* __restrict__ out_c) {
    int idx = blockIdx.x * blockDim.x + threadIdx.x;
    if (idx >= BDIM * HDIM) return;
    int b = idx / HDIM;
    int j = idx - b * HDIM;

    const float* gr = g_gates_r + (size_t)b * G4;
    const float* gl = g_gates_l + (size_t)b * G4;

    float ig = gr[j];
    float fg = gr[HDIM + j];
    float gg = gr[2 * HDIM + j];
    float og = gr[3 * HDIM + j];

    int p = pos[b];
    float cprev = stack_cell[((size_t)b * SDIM + p) * HDIM + j];
    float cr = sigf(fg) * cprev + sigf(ig) * tanhf(gg);
    float hr = sigf(og) * tanhf(cr);

    // left LSTM: zero initial state -> c_l = sig(i)*tanh(g)
    float cl = sigf(gl[j]) * tanhf(gl[2 * HDIM + j]);
    float hl = sigf(gl[3 * HDIM + j]) * tanhf(cl);

    g_hlcat[(size_t)b * (2 * HDIM) + j]        = hr;
    g_hlcat[(size_t)b * (2 * HDIM) + HDIM + j] = hl;

    size_t off = ((size_t)b * SDIM + p + 1) * HDIM + j;
    out_h[off] = hr;
    out_c[off] = cr;
}

// ---------------------------------------------------------------------------
extern "C" void kernel_launch(void* const* d_in, const int* in_sizes, int n_in,
                              void* d_out, int out_size) {
    const float* ch     = (const float*)d_in[0];   // char        (B, I)
    const float* sh     = (const float*)d_in[1];   // stack_hidden(B, S, H)
    const float* sc     = (const float*)d_in[2];   // stack_cell  (B, S, H)
    const int*   pos    = (const int*)d_in[3];     // (B,)
    const float* W_ih_r = (const float*)d_in[4];   // (4H, I)
    const float* W_hh_r = (const float*)d_in[5];   // (4H, H)
    const float* b_ih_r = (const float*)d_in[6];
    const float* b_hh_r = (const float*)d_in[7];
    const float* W_ih_l = (const float*)d_in[8];
    const float* W_hh_l = (const float*)d_in[9];   (void)W_hh_l;  // h=0, unused
    const float* b_ih_l = (const float*)d_in[10];
    const float* b_hh_l = (const float*)d_in[11];
    const float* W_comp = (const float*)d_in[12];  // (H, 2H)
    const float* b_comp = (const float*)d_in[13];

    float* out      = (float*)d_out;
    float* out_sub  = out;                                    // (B, H)
    float* out_h    = out + (size_t)BDIM * HDIM;              // (B, S, H)
    float* out_c    = out_h + (size_t)BDIM * SDIM * HDIM;     // (B, S, H)

    // 1) copy both stacks to output (bulk, float4)
    {
        size_t n4 = (size_t)BDIM * SDIM * HDIM / 4;   // 33,816,576
        int threads = 256;
        int blocks  = (int)((n4 + (size_t)threads * 8 - 1) / ((size_t)threads * 8));
        copy_stacks_kernel<<<blocks, threads>>>(
            (const float4*)sh, (const float4*)sc,
            (float4*)out_h, (float4*)out_c, n4);
    }

    // 2) gather A_cat = [char | h@pos]
    {
        int total = BDIM * (HDIM / 4);
        gather_kernel<<<(total + 255) / 256, 256>>>(ch, sh, pos);
    }

    float* gAcat;    cudaGetSymbolAddress((void**)&gAcat,    g_Acat);
    float* gGatesR;  cudaGetSymbolAddress((void**)&gGatesR,  g_gates_r);
    float* gGatesL;  cudaGetSymbolAddress((void**)&gGatesL,  g_gates_l);
    float* gHlcat;   cudaGetSymbolAddress((void**)&gHlcat,   g_hlcat);

    // 3) gates_r = [char|h] @ [W_ih_r ; W_hh_r]^T + b_ih_r + b_hh_r
    {
        dim3 grid(G4 / BN, BDIM / BM);   // (32, 8)
        gemm_ws_kernel<<<grid, 256>>>(gAcat, W_ih_r, W_hh_r, IDIM, IDIM + HDIM,
                                      b_ih_r, b_hh_r, gGatesR, G4, 0);
    }

    // 4) gates_l = char @ W_ih_l^T + b_ih_l + b_hh_l   (h=0 -> W_hh_l drops)
    {
        dim3 grid(G4 / BN, BDIM / BM);
        gemm_ws_kernel<<<grid, 256>>>(ch, W_ih_l, nullptr, IDIM, IDIM,
                                      b_ih_l, b_hh_l, gGatesL, G4, 0);
    }

    // 5) elementwise LSTM cells + scatter (pos+1) + build [h_r|h_l]
    {
        int total = BDIM * HDIM;
        lstm_elem_kernel<<<(total + 255) / 256, 256>>>(sc, pos, out_h, out_c);
    }

    // 6) subword = tanh([h_r|h_l] @ W_comp^T + b_comp) -> d_out
    {
        dim3 grid(HDIM / BN, BDIM / BM);  // (8, 8)
        gemm_ws_kernel<<<grid, 256>>>(gHlcat, W_comp, nullptr, 2 * HDIM, 2 * HDIM,
                                      b_comp, nullptr, out_sub, HDIM, 1);
    }
}